// round 16
// baseline (speedup 1.0000x reference)
#include <cuda_runtime.h>
#include <cuda_fp16.h>
#include <cstdint>

#define D_MODEL 512
#define NH 8
#define DH 64

// Scratch (allocation-free rule: __device__ globals).
__device__ __half g_qh[4096 * 512];
__device__ __half g_kh[4096 * 512];
__device__ __half g_vh[4096 * 512];
__device__ __half g_ah[4096 * 512];
__device__ __half g_xh[3 * 4096 * 512];   // half-converted raw q,k,v inputs
__device__ __half g_wh[4 * 512 * 512];    // half-converted weights
// Split-KV partials (fp32): up to 4 chunks per q-row (chunk = 8 kb-iters).
__device__ float g_op[4 * 4096 * 512];
__device__ float g_m[4 * 8 * 4096];
__device__ float g_l[4 * 8 * 4096];

// Work-item tables, HEAVY-FIRST (LPT). (qb, ch); chunk = [8ch, min(8ch+7, 2qb+1)].
__constant__ unsigned char c_qb[40] = {
    3, 4, 5, 6, 7, 7, 8, 8, 9, 9, 10, 10, 11, 11, 11, 12, 12, 12,
    13, 13, 13, 14, 14, 14, 15, 15, 15, 15,
    2, 6, 10, 14, 1, 5, 9, 13, 0, 4, 8, 12};
__constant__ unsigned char c_ch[40] = {
    0, 0, 0, 0, 0, 1, 0, 1, 0, 1, 0, 1, 0, 1, 2, 0, 1, 2,
    0, 1, 2, 0, 1, 2, 0, 1, 2, 3,
    0, 1, 2, 3, 0, 1, 2, 3, 0, 1, 2, 3};

__device__ __forceinline__ void mma_f16(float* c, uint32_t a0, uint32_t a1,
                                        uint32_t a2, uint32_t a3, uint32_t b0,
                                        uint32_t b1) {
    asm volatile(
        "mma.sync.aligned.m16n8k16.row.col.f32.f16.f16.f32 "
        "{%0,%1,%2,%3}, {%4,%5,%6,%7}, {%8,%9}, {%0,%1,%2,%3};"
        : "+f"(c[0]), "+f"(c[1]), "+f"(c[2]), "+f"(c[3])
        : "r"(a0), "r"(a1), "r"(a2), "r"(a3), "r"(b0), "r"(b1));
}

__device__ __forceinline__ uint32_t ld_u32h(const __half* p) {
    return *(const uint32_t*)p;
}
__device__ __forceinline__ uint32_t pk2h(float x, float y) {
    __half2 h = __floats2half2_rn(x, y);  // .x = x in low 16 bits
    return *(uint32_t*)&h;
}

__device__ __forceinline__ void cp_async16(void* smem_dst, const void* gmem_src) {
    uint32_t s = (uint32_t)__cvta_generic_to_shared(smem_dst);
    asm volatile("cp.async.cg.shared.global [%0], [%1], 16;\n" ::"r"(s),
                 "l"(gmem_src));
}
#define CP_COMMIT() asm volatile("cp.async.commit_group;\n" ::: "memory")
#define CP_WAIT0() asm volatile("cp.async.wait_group 0;\n" ::: "memory")

// ---------------------------------------------------------------------------
// Convert weights / inputs fp32 -> half (RN) once.
// ---------------------------------------------------------------------------
__global__ void __launch_bounds__(256) conv_w(const float4* __restrict__ w0,
                                              const float4* __restrict__ w1,
                                              const float4* __restrict__ w2,
                                              const float4* __restrict__ w3,
                                              __half* __restrict__ out) {
    const int i = blockIdx.x * 256 + threadIdx.x;  // 0..262143 float4
    const int which = i >> 16;
    const int j = i & 65535;
    const float4 v = (which == 0) ? w0[j] : (which == 1) ? w1[j]
                     : (which == 2) ? w2[j] : w3[j];
    __half2 h01 = __floats2half2_rn(v.x, v.y);
    __half2 h23 = __floats2half2_rn(v.z, v.w);
    uint2 o;
    o.x = *(uint32_t*)&h01;
    o.y = *(uint32_t*)&h23;
    *(uint2*)(out + (size_t)i * 4) = o;
}

__global__ void __launch_bounds__(256) conv_in(const float4* __restrict__ a0,
                                               const float4* __restrict__ a1,
                                               const float4* __restrict__ a2,
                                               __half* __restrict__ out) {
    const int i = blockIdx.x * 256 + threadIdx.x;  // 0..1572863 float4
    const int which = i / 524288;
    const int j = i % 524288;
    const float4 v = (which == 0) ? a0[j] : (which == 1) ? a1[j] : a2[j];
    __half2 h01 = __floats2half2_rn(v.x, v.y);
    __half2 h23 = __floats2half2_rn(v.z, v.w);
    uint2 o;
    o.x = *(uint32_t*)&h01;
    o.y = *(uint32_t*)&h23;
    *(uint2*)(out + (size_t)i * 4) = o;
}

// ---------------------------------------------------------------------------
// fp16 GEMM: C[M,512] = A[M,512] @ W[512,512]^T  via mma.m16n8k16.
// BM=BN=128, BK=64 (halves), 2-stage cp.async. 256 thr = 8 warps (2m x 4n),
// warp tile 64x32. A and W are half (pre-converted). blockIdx.z selects one
// of 3 (A, W, C) triples. OUT_FLOAT: write fp32 (final output) else half.
// Smem row stride 72 halves (144 B) -> conflict-free u32 fragment loads.
// ---------------------------------------------------------------------------
#define GSTRH 72
#define SMEM_GEMMH (2 * 2 * 128 * GSTRH * 2)

template <int OUT_FLOAT>
__global__ void __launch_bounds__(256, 2)
    gemm_h(const __half* __restrict__ A0, const __half* __restrict__ W0,
           void* __restrict__ C0, const __half* __restrict__ A1,
           const __half* __restrict__ W1, void* __restrict__ C1,
           const __half* __restrict__ A2, const __half* __restrict__ W2,
           void* __restrict__ C2) {
    extern __shared__ __half smh[];
    __half* As = smh;                      // [2][128][GSTRH]
    __half* Ws = smh + 2 * 128 * GSTRH;    // [2][128][GSTRH]

    const int z = blockIdx.z;
    const __half* A = (z == 0) ? A0 : (z == 1) ? A1 : A2;
    const __half* W = (z == 0) ? W0 : (z == 1) ? W1 : W2;
    void* C = (z == 0) ? C0 : (z == 1) ? C1 : C2;

    const int tid = threadIdx.x;
    const int lane = tid & 31, wid = tid >> 5;
    const int g = lane >> 2, tg = lane & 3;
    const int warp_m = wid >> 2, warp_n = wid & 3;
    const int row0 = blockIdx.x * 128, col0 = blockIdx.y * 128;

    float acc[4][4][4];
#pragma unroll
    for (int mi = 0; mi < 4; mi++)
#pragma unroll
        for (int ni = 0; ni < 4; ni++)
#pragma unroll
            for (int c = 0; c < 4; c++) acc[mi][ni][c] = 0.f;

    auto load_stage = [&](int k0, int st) {
        __half* Ad = As + st * 128 * GSTRH;
        __half* Wd = Ws + st * 128 * GSTRH;
#pragma unroll
        for (int i = 0; i < 4; i++) {
            const int f = tid + i * 256;      // 1024 16B-chunks per matrix
            const int r = f >> 3, c8 = (f & 7) * 8;
            cp_async16(Ad + r * GSTRH + c8, A + (size_t)(row0 + r) * D_MODEL + k0 + c8);
            cp_async16(Wd + r * GSTRH + c8, W + (size_t)(col0 + r) * D_MODEL + k0 + c8);
        }
        CP_COMMIT();
    };

    load_stage(0, 0);

    for (int it = 0; it < 8; it++) {
        CP_WAIT0();
        __syncthreads();
        if (it + 1 < 8) load_stage((it + 1) * 64, (it + 1) & 1);

        const __half* Ab = As + (it & 1) * 128 * GSTRH;
        const __half* Wb = Ws + (it & 1) * 128 * GSTRH;
#pragma unroll
        for (int s = 0; s < 4; s++) {
            const int kk = s * 16;
            uint32_t a[4][4];
#pragma unroll
            for (int mi = 0; mi < 4; mi++) {
                const int rm = warp_m * 64 + mi * 16;
                a[mi][0] = ld_u32h(Ab + (rm + g) * GSTRH + kk + 2 * tg);
                a[mi][1] = ld_u32h(Ab + (rm + 8 + g) * GSTRH + kk + 2 * tg);
                a[mi][2] = ld_u32h(Ab + (rm + g) * GSTRH + kk + 2 * tg + 8);
                a[mi][3] = ld_u32h(Ab + (rm + 8 + g) * GSTRH + kk + 2 * tg + 8);
            }
#pragma unroll
            for (int ni = 0; ni < 4; ni++) {
                const int nb = warp_n * 32 + ni * 8;
                uint32_t b0 = ld_u32h(Wb + (nb + g) * GSTRH + kk + 2 * tg);
                uint32_t b1 = ld_u32h(Wb + (nb + g) * GSTRH + kk + 2 * tg + 8);
#pragma unroll
                for (int mi = 0; mi < 4; mi++)
                    mma_f16(acc[mi][ni], a[mi][0], a[mi][1], a[mi][2], a[mi][3],
                            b0, b1);
            }
        }
    }

#pragma unroll
    for (int mi = 0; mi < 4; mi++) {
#pragma unroll
        for (int ni = 0; ni < 4; ni++) {
            const int r = row0 + warp_m * 64 + mi * 16 + g;
            const int c = col0 + warp_n * 32 + ni * 8 + 2 * tg;
            if (OUT_FLOAT) {
                float* Cf = (float*)C;
                *(float2*)(Cf + (size_t)r * D_MODEL + c) =
                    make_float2(acc[mi][ni][0], acc[mi][ni][1]);
                *(float2*)(Cf + (size_t)(r + 8) * D_MODEL + c) =
                    make_float2(acc[mi][ni][2], acc[mi][ni][3]);
            } else {
                __half* Ch = (__half*)C;
                __half2 h01 = __floats2half2_rn(acc[mi][ni][0], acc[mi][ni][1]);
                __half2 h23 = __floats2half2_rn(acc[mi][ni][2], acc[mi][ni][3]);
                *(__half2*)(Ch + (size_t)r * D_MODEL + c) = h01;
                *(__half2*)(Ch + (size_t)(r + 8) * D_MODEL + c) = h23;
            }
        }
    }
}

// ---------------------------------------------------------------------------
// Split-KV flash attention, fp16 mma (m16n8k16). Br=128, Bc=64, 128 threads
// = 4 warps, warp owns 32 q-rows (two 16-row mma tiles). Q/K/V half in smem
// (stride 72 halves, conflict-free). PV: P fragments come straight from the
// lane's own S accumulator (k16 alignment -> NO shuffles); V B-fragments via
// ldmatrix.x2.trans. Softmax/accum fp32. LPT item-major mapping.
// ---------------------------------------------------------------------------
#define ASTR 72
#define SMEM_ATTNH ((128 + 128 + 128) * ASTR * 2)

__global__ void __launch_bounds__(128, 2)
    attn_kernel(const __half* __restrict__ Qg, const __half* __restrict__ Kg,
                const __half* __restrict__ Vg, float* __restrict__ Op,
                float* __restrict__ Mp, float* __restrict__ Lp, int SEQ) {
    extern __shared__ __half smb[];
    __half* Qs = smb;                       // [128][ASTR]
    __half* Ks = smb + 128 * ASTR;          // [2][64][ASTR]
    __half* Vs = Ks + 2 * 64 * ASTR;        // [2][64][ASTR]

    const float inv_scale = 0.044194173824159216f;  // 1/sqrt(512)
    const int tid = threadIdx.x;
    const int lane = tid & 31, wid = tid >> 5;
    const int g = lane >> 2, tg = lane & 3;
    const int r0 = wid * 32;                 // warp's 32 q-rows
    const int bh = blockIdx.x & 15;
    const int item = blockIdx.x >> 4;
    const int qb = c_qb[item];
    const int ch = c_ch[item];
    const int b = bh >> 3, h = bh & 7;
    const size_t rowbase = (size_t)b * SEQ;
    const int colh = h * DH;
    const int kbmax = 2 * qb + 1;
    const int kb0 = ch * 8;
    const int kbe = min(kb0 + 7, kbmax);

    auto load_kv = [&](int kb, int st) {
        const __half* Kb = Kg + (rowbase + kb * 64) * D_MODEL + colh;
        const __half* Vb = Vg + (rowbase + kb * 64) * D_MODEL + colh;
        __half* Kd = Ks + st * 64 * ASTR;
        __half* Vd = Vs + st * 64 * ASTR;
#pragma unroll
        for (int i = 0; i < 4; i++) {
            const int f = tid + i * 128;      // 512 16B-chunks per matrix
            const int r = f >> 3, c8 = (f & 7) * 8;
            cp_async16(Kd + r * ASTR + c8, Kb + (size_t)r * D_MODEL + c8);
            cp_async16(Vd + r * ASTR + c8, Vb + (size_t)r * D_MODEL + c8);
        }
        CP_COMMIT();
    };

    load_kv(kb0, kb0 & 1);

    // Stage Q tile [128 x 64] halves (1024 16B-chunks).
#pragma unroll
    for (int i = 0; i < 8; i++) {
        const int f = tid + i * 128;
        const int r = f >> 3, c8 = (f & 7) * 8;
        float4 v = *(const float4*)(Qg + (rowbase + qb * 128 + r) * D_MODEL + colh + c8);
        *(float4*)(Qs + r * ASTR + c8) = v;
    }

    float m[4] = {-1e30f, -1e30f, -1e30f, -1e30f};
    float l[4] = {0.f, 0.f, 0.f, 0.f};
    float oacc[8][2][4];
#pragma unroll
    for (int ni = 0; ni < 8; ni++)
#pragma unroll
        for (int rt = 0; rt < 2; rt++)
#pragma unroll
            for (int c = 0; c < 4; c++) oacc[ni][rt][c] = 0.f;

    for (int kb = kb0; kb <= kbe; kb++) {
        CP_WAIT0();
        __syncthreads();
        if (kb + 1 <= kbe) load_kv(kb + 1, (kb + 1) & 1);

        const __half* Kb = Ks + (kb & 1) * 64 * ASTR;
        const __half* Vb = Vs + (kb & 1) * 64 * ASTR;
        const uint32_t vb_base = (uint32_t)__cvta_generic_to_shared(Vb);

        const int joff = kb * 64 - qb * 128;
        if (joff > r0 + 31) continue;           // warp fully masked
        const bool need_mask = (joff + 63 > r0);

        float sacc[8][2][4];
#pragma unroll
        for (int ni = 0; ni < 8; ni++)
#pragma unroll
            for (int rt = 0; rt < 2; rt++)
#pragma unroll
                for (int c = 0; c < 4; c++) sacc[ni][rt][c] = 0.f;

        // S = Q K^T : 4 k16-steps over dh=64. K fragments shared across rt.
#pragma unroll
        for (int ks = 0; ks < 4; ks++) {
            const int kk = ks * 16;
            uint32_t a[2][4];
#pragma unroll
            for (int rt = 0; rt < 2; rt++) {
                const int rr = r0 + rt * 16;
                a[rt][0] = ld_u32h(Qs + (rr + g) * ASTR + kk + 2 * tg);
                a[rt][1] = ld_u32h(Qs + (rr + 8 + g) * ASTR + kk + 2 * tg);
                a[rt][2] = ld_u32h(Qs + (rr + g) * ASTR + kk + 2 * tg + 8);
                a[rt][3] = ld_u32h(Qs + (rr + 8 + g) * ASTR + kk + 2 * tg + 8);
            }
#pragma unroll
            for (int ni = 0; ni < 8; ni++) {
                uint32_t b0 = ld_u32h(Kb + (ni * 8 + g) * ASTR + kk + 2 * tg);
                uint32_t b1 = ld_u32h(Kb + (ni * 8 + g) * ASTR + kk + 2 * tg + 8);
                mma_f16(sacc[ni][0], a[0][0], a[0][1], a[0][2], a[0][3], b0, b1);
                mma_f16(sacc[ni][1], a[1][0], a[1][1], a[1][2], a[1][3], b0, b1);
            }
        }

        // scale + causal mask ((x-1e10)/scale underflows expf to 0 == -1e30)
#pragma unroll
        for (int ni = 0; ni < 8; ni++)
#pragma unroll
            for (int rt = 0; rt < 2; rt++)
#pragma unroll
                for (int c = 0; c < 4; c++) {
                    float sv = sacc[ni][rt][c] * inv_scale;
                    if (need_mask) {
                        const int j = joff + ni * 8 + 2 * tg + (c & 1);
                        const int r = r0 + rt * 16 + (c >> 1) * 8 + g;
                        if (j > r) sv = -1e30f;
                    }
                    sacc[ni][rt][c] = sv;
                }

        // online softmax per row-group rg = rt*2 + (c>>1)
#pragma unroll
        for (int rg = 0; rg < 4; rg++) {
            const int rt = rg >> 1, ci = (rg & 1) * 2;
            float rmax = -1e30f;
#pragma unroll
            for (int ni = 0; ni < 8; ni++)
                rmax = fmaxf(rmax, fmaxf(sacc[ni][rt][ci], sacc[ni][rt][ci + 1]));
            rmax = fmaxf(rmax, __shfl_xor_sync(0xffffffffu, rmax, 1));
            rmax = fmaxf(rmax, __shfl_xor_sync(0xffffffffu, rmax, 2));
            const float mnew = fmaxf(m[rg], rmax);
            const float corr = __expf(m[rg] - mnew);
            float rsum = 0.f;
#pragma unroll
            for (int ni = 0; ni < 8; ni++) {
                float p0 = __expf(sacc[ni][rt][ci] - mnew);
                float p1 = __expf(sacc[ni][rt][ci + 1] - mnew);
                sacc[ni][rt][ci] = p0;
                sacc[ni][rt][ci + 1] = p1;
                rsum += p0 + p1;
            }
            rsum += __shfl_xor_sync(0xffffffffu, rsum, 1);
            rsum += __shfl_xor_sync(0xffffffffu, rsum, 2);
            l[rg] = l[rg] * corr + rsum;
            m[rg] = mnew;
#pragma unroll
            for (int ni = 0; ni < 8; ni++) {
                oacc[ni][rt][ci] *= corr;
                oacc[ni][rt][ci + 1] *= corr;
            }
        }

        // O += P V : A-frags directly from lane-local sacc (k16 alignment);
        // V B-frags via ldmatrix.x2.trans. j = k dimension (4 k16-steps).
#pragma unroll
        for (int ks = 0; ks < 4; ks++) {
            const int j0 = ks * 16;
            uint32_t aA[2][4];
#pragma unroll
            for (int rt = 0; rt < 2; rt++) {
                aA[rt][0] = pk2h(sacc[2 * ks][rt][0], sacc[2 * ks][rt][1]);
                aA[rt][1] = pk2h(sacc[2 * ks][rt][2], sacc[2 * ks][rt][3]);
                aA[rt][2] = pk2h(sacc[2 * ks + 1][rt][0], sacc[2 * ks + 1][rt][1]);
                aA[rt][3] = pk2h(sacc[2 * ks + 1][rt][2], sacc[2 * ks + 1][rt][3]);
            }
            const uint32_t row_addr =
                vb_base + ((j0 + (lane & 15)) * ASTR) * 2;
#pragma unroll
            for (int ni = 0; ni < 8; ni++) {
                uint32_t b0, b1;
                asm volatile(
                    "ldmatrix.sync.aligned.m8n8.x2.trans.shared.b16 {%0,%1}, [%2];"
                    : "=r"(b0), "=r"(b1)
                    : "r"(row_addr + ni * 16));
                mma_f16(oacc[ni][0], aA[0][0], aA[0][1], aA[0][2], aA[0][3], b0, b1);
                mma_f16(oacc[ni][1], aA[1][0], aA[1][1], aA[1][2], aA[1][3], b0, b1);
            }
        }
    }

    // Write UNNORMALIZED fp32 partials + (m, l)
    float* op = Op + (size_t)ch * 4096 * 512;
#pragma unroll
    for (int rt = 0; rt < 2; rt++) {
        const size_t rA = rowbase + qb * 128 + r0 + rt * 16 + g;
#pragma unroll
        for (int ni = 0; ni < 8; ni++) {
            const int c = colh + ni * 8 + 2 * tg;
            *(float2*)(op + rA * D_MODEL + c) =
                make_float2(oacc[ni][rt][0], oacc[ni][rt][1]);
            *(float2*)(op + (rA + 8) * D_MODEL + c) =
                make_float2(oacc[ni][rt][2], oacc[ni][rt][3]);
        }
        if (tg == 0) {
            const size_t mlb = (size_t)(ch * 8 + h) * 4096;
            Mp[mlb + rA] = m[rt * 2];
            Lp[mlb + rA] = l[rt * 2];
            Mp[mlb + rA + 8] = m[rt * 2 + 1];
            Lp[mlb + rA + 8] = l[rt * 2 + 1];
        }
    }
}

// ---------------------------------------------------------------------------
// Combine split-KV partials: exact softmax merge, normalize, store half.
// ---------------------------------------------------------------------------
__global__ void __launch_bounds__(256) combine_kernel(
    const float* __restrict__ Op, const float* __restrict__ Mp,
    const float* __restrict__ Lp, __half* __restrict__ Og) {
    const int tid = threadIdx.x;
    const int u = blockIdx.x * 8 + (tid >> 5);  // (row, head) unit
    const int row = u >> 3, h = u & 7;
    const int j = (tid & 31) * 2;
    const int qb = (row >> 7) & 15;
    const int nch = (qb >> 2) + 1;

    float mv[4], lv[4];
    float mg = -1e30f;
#pragma unroll
    for (int c = 0; c < 4; c++)
        if (c < nch) {
            mv[c] = Mp[(size_t)(c * 8 + h) * 4096 + row];
            lv[c] = Lp[(size_t)(c * 8 + h) * 4096 + row];
            mg = fmaxf(mg, mv[c]);
        }
    float lg = 0.f;
    float2 o = make_float2(0.f, 0.f);
#pragma unroll
    for (int c = 0; c < 4; c++)
        if (c < nch) {
            const float sc = __expf(mv[c] - mg);
            lg += sc * lv[c];
            float2 p = *(const float2*)(Op + (size_t)c * 4096 * 512 +
                                        (size_t)row * 512 + h * 64 + j);
            o.x += sc * p.x;
            o.y += sc * p.y;
        }
    const float inv = 1.f / lg;
    *(__half2*)(Og + (size_t)row * 512 + h * 64 + j) =
        __floats2half2_rn(o.x * inv, o.y * inv);
}

// ---------------------------------------------------------------------------
extern "C" void kernel_launch(void* const* d_in, const int* in_sizes, int n_in,
                              void* d_out, int out_size) {
    const float* q  = (const float*)d_in[0];
    const float* k  = (const float*)d_in[1];
    const float* v  = (const float*)d_in[2];
    const float* wq = (const float*)d_in[3];
    const float* wk = (const float*)d_in[4];
    const float* wv = (const float*)d_in[5];
    const float* wo = (const float*)d_in[6];
    float* out = (float*)d_out;

    const int M = in_sizes[0] / D_MODEL;  // B*S = 4096
    const int B = 2;
    const int SEQ = M / B;                // 2048

    __half *gqh, *gkh, *gvh, *gah, *gxh, *gwh;
    float *gop, *gm, *gl;
    cudaGetSymbolAddress((void**)&gqh, g_qh);
    cudaGetSymbolAddress((void**)&gkh, g_kh);
    cudaGetSymbolAddress((void**)&gvh, g_vh);
    cudaGetSymbolAddress((void**)&gah, g_ah);
    cudaGetSymbolAddress((void**)&gxh, g_xh);
    cudaGetSymbolAddress((void**)&gwh, g_wh);
    cudaGetSymbolAddress((void**)&gop, g_op);
    cudaGetSymbolAddress((void**)&gm, g_m);
    cudaGetSymbolAddress((void**)&gl, g_l);

    cudaFuncSetAttribute(gemm_h<0>, cudaFuncAttributeMaxDynamicSharedMemorySize,
                         SMEM_GEMMH);
    cudaFuncSetAttribute(gemm_h<1>, cudaFuncAttributeMaxDynamicSharedMemorySize,
                         SMEM_GEMMH);
    cudaFuncSetAttribute(attn_kernel, cudaFuncAttributeMaxDynamicSharedMemorySize,
                         SMEM_ATTNH);

    // Convert weights + inputs fp32 -> half (RN).
    conv_w<<<1024, 256>>>((const float4*)wq, (const float4*)wk,
                          (const float4*)wv, (const float4*)wo, gwh);
    conv_in<<<6144, 256>>>((const float4*)q, (const float4*)k, (const float4*)v,
                           gxh);
    const __half* xq = gxh;
    const __half* xk = gxh + 2097152;
    const __half* xv = gxh + 4194304;
    const __half* hwq = gwh;
    const __half* hwk = gwh + 512 * 512;
    const __half* hwv = gwh + 2 * 512 * 512;
    const __half* hwo = gwh + 3 * 512 * 512;

    // Fused projections (fp16 mma), half outputs.
    dim3 gg3(M / 128, D_MODEL / 128, 3);
    gemm_h<0><<<gg3, 256, SMEM_GEMMH>>>(xq, hwq, gqh, xk, hwk, gkh, xv, hwv, gvh);

    // Split-KV attention: 40 heavy-first items x 16 bh (item-major), 128 thr.
    attn_kernel<<<16 * 40, 128, SMEM_ATTNH>>>(gqh, gkh, gvh, gop, gm, gl, SEQ);

    // Combine partials -> half attn output.
    combine_kernel<<<4096 * 8 / 8, 256>>>(gop, gm, gl, gah);

    // Output projection (fp16 mma), fp32 output.
    dim3 gg1(M / 128, D_MODEL / 128, 1);
    gemm_h<1><<<gg1, 256, SMEM_GEMMH>>>(gah, hwo, out, gah, hwo, out, gah, hwo,
                                        out);
}

// round 17
// speedup vs baseline: 1.0429x; 1.0429x over previous
#include <cuda_runtime.h>
#include <cuda_fp16.h>
#include <cstdint>

#define D_MODEL 512
#define NH 8
#define DH 64

// Scratch (allocation-free rule: __device__ globals).
__device__ __half g_qh[4096 * 512];
__device__ __half g_kh[4096 * 512];
__device__ __half g_vh[4096 * 512];
__device__ __half g_ah[4096 * 512];
__device__ __half g_xh[3 * 4096 * 512];   // half-converted raw q,k,v inputs
__device__ __half g_wh[4 * 512 * 512];    // half-converted weights
// Split-KV partials: O as half (m/l fp32). Up to 4 chunks per q-row.
__device__ __half g_oph[4 * 4096 * 512];
__device__ float g_m[4 * 8 * 4096];
__device__ float g_l[4 * 8 * 4096];

// Work-item tables, HEAVY-FIRST (LPT). (qb, ch); chunk = [8ch, min(8ch+7, 2qb+1)].
__constant__ unsigned char c_qb[40] = {
    3, 4, 5, 6, 7, 7, 8, 8, 9, 9, 10, 10, 11, 11, 11, 12, 12, 12,
    13, 13, 13, 14, 14, 14, 15, 15, 15, 15,
    2, 6, 10, 14, 1, 5, 9, 13, 0, 4, 8, 12};
__constant__ unsigned char c_ch[40] = {
    0, 0, 0, 0, 0, 1, 0, 1, 0, 1, 0, 1, 0, 1, 2, 0, 1, 2,
    0, 1, 2, 0, 1, 2, 0, 1, 2, 3,
    0, 1, 2, 3, 0, 1, 2, 3, 0, 1, 2, 3};

__device__ __forceinline__ void mma_f16(float* c, uint32_t a0, uint32_t a1,
                                        uint32_t a2, uint32_t a3, uint32_t b0,
                                        uint32_t b1) {
    asm volatile(
        "mma.sync.aligned.m16n8k16.row.col.f32.f16.f16.f32 "
        "{%0,%1,%2,%3}, {%4,%5,%6,%7}, {%8,%9}, {%0,%1,%2,%3};"
        : "+f"(c[0]), "+f"(c[1]), "+f"(c[2]), "+f"(c[3])
        : "r"(a0), "r"(a1), "r"(a2), "r"(a3), "r"(b0), "r"(b1));
}

__device__ __forceinline__ uint32_t ld_u32h(const __half* p) {
    return *(const uint32_t*)p;
}
__device__ __forceinline__ uint32_t pk2h(float x, float y) {
    __half2 h = __floats2half2_rn(x, y);  // .x = x in low 16 bits
    return *(uint32_t*)&h;
}

__device__ __forceinline__ void cp_async16(void* smem_dst, const void* gmem_src) {
    uint32_t s = (uint32_t)__cvta_generic_to_shared(smem_dst);
    asm volatile("cp.async.cg.shared.global [%0], [%1], 16;\n" ::"r"(s),
                 "l"(gmem_src));
}
#define CP_COMMIT() asm volatile("cp.async.commit_group;\n" ::: "memory")
#define CP_WAIT0() asm volatile("cp.async.wait_group 0;\n" ::: "memory")

// ---------------------------------------------------------------------------
// Convert weights / inputs fp32 -> half (RN) once.
// ---------------------------------------------------------------------------
__global__ void __launch_bounds__(256) conv_w(const float4* __restrict__ w0,
                                              const float4* __restrict__ w1,
                                              const float4* __restrict__ w2,
                                              const float4* __restrict__ w3,
                                              __half* __restrict__ out) {
    const int i = blockIdx.x * 256 + threadIdx.x;  // 0..262143 float4
    const int which = i >> 16;
    const int j = i & 65535;
    const float4 v = (which == 0) ? w0[j] : (which == 1) ? w1[j]
                     : (which == 2) ? w2[j] : w3[j];
    __half2 h01 = __floats2half2_rn(v.x, v.y);
    __half2 h23 = __floats2half2_rn(v.z, v.w);
    uint2 o;
    o.x = *(uint32_t*)&h01;
    o.y = *(uint32_t*)&h23;
    *(uint2*)(out + (size_t)i * 4) = o;
}

__global__ void __launch_bounds__(256) conv_in(const float4* __restrict__ a0,
                                               const float4* __restrict__ a1,
                                               const float4* __restrict__ a2,
                                               __half* __restrict__ out) {
    const int i = blockIdx.x * 256 + threadIdx.x;  // 0..1572863 float4
    const int which = i / 524288;
    const int j = i % 524288;
    const float4 v = (which == 0) ? a0[j] : (which == 1) ? a1[j] : a2[j];
    __half2 h01 = __floats2half2_rn(v.x, v.y);
    __half2 h23 = __floats2half2_rn(v.z, v.w);
    uint2 o;
    o.x = *(uint32_t*)&h01;
    o.y = *(uint32_t*)&h23;
    *(uint2*)(out + (size_t)i * 4) = o;
}

// ---------------------------------------------------------------------------
// fp16 GEMM: C[M,512] = A[M,512] @ W[512,512]^T  via mma.m16n8k16.
// BM=BN=128, BK=64 (halves), 2-stage cp.async. 256 thr = 8 warps (2m x 4n),
// warp tile 64x32. blockIdx.z selects one of 3 (A, W, C) triples.
// scale_z0 multiplies the z==0 accumulator before output (used to fold the
// attention 1/sqrt(d) into the Q projection for free).
// ---------------------------------------------------------------------------
#define GSTRH 72
#define SMEM_GEMMH (2 * 2 * 128 * GSTRH * 2)

template <int OUT_FLOAT>
__global__ void __launch_bounds__(256, 2)
    gemm_h(const __half* __restrict__ A0, const __half* __restrict__ W0,
           void* __restrict__ C0, const __half* __restrict__ A1,
           const __half* __restrict__ W1, void* __restrict__ C1,
           const __half* __restrict__ A2, const __half* __restrict__ W2,
           void* __restrict__ C2, float scale_z0) {
    extern __shared__ __half smh[];
    __half* As = smh;                      // [2][128][GSTRH]
    __half* Ws = smh + 2 * 128 * GSTRH;    // [2][128][GSTRH]

    const int z = blockIdx.z;
    const __half* A = (z == 0) ? A0 : (z == 1) ? A1 : A2;
    const __half* W = (z == 0) ? W0 : (z == 1) ? W1 : W2;
    void* C = (z == 0) ? C0 : (z == 1) ? C1 : C2;
    const float sc = (z == 0) ? scale_z0 : 1.f;

    const int tid = threadIdx.x;
    const int lane = tid & 31, wid = tid >> 5;
    const int g = lane >> 2, tg = lane & 3;
    const int warp_m = wid >> 2, warp_n = wid & 3;
    const int row0 = blockIdx.x * 128, col0 = blockIdx.y * 128;

    float acc[4][4][4];
#pragma unroll
    for (int mi = 0; mi < 4; mi++)
#pragma unroll
        for (int ni = 0; ni < 4; ni++)
#pragma unroll
            for (int c = 0; c < 4; c++) acc[mi][ni][c] = 0.f;

    auto load_stage = [&](int k0, int st) {
        __half* Ad = As + st * 128 * GSTRH;
        __half* Wd = Ws + st * 128 * GSTRH;
#pragma unroll
        for (int i = 0; i < 4; i++) {
            const int f = tid + i * 256;      // 1024 16B-chunks per matrix
            const int r = f >> 3, c8 = (f & 7) * 8;
            cp_async16(Ad + r * GSTRH + c8, A + (size_t)(row0 + r) * D_MODEL + k0 + c8);
            cp_async16(Wd + r * GSTRH + c8, W + (size_t)(col0 + r) * D_MODEL + k0 + c8);
        }
        CP_COMMIT();
    };

    load_stage(0, 0);

    for (int it = 0; it < 8; it++) {
        CP_WAIT0();
        __syncthreads();
        if (it + 1 < 8) load_stage((it + 1) * 64, (it + 1) & 1);

        const __half* Ab = As + (it & 1) * 128 * GSTRH;
        const __half* Wb = Ws + (it & 1) * 128 * GSTRH;
#pragma unroll
        for (int s = 0; s < 4; s++) {
            const int kk = s * 16;
            uint32_t a[4][4];
#pragma unroll
            for (int mi = 0; mi < 4; mi++) {
                const int rm = warp_m * 64 + mi * 16;
                a[mi][0] = ld_u32h(Ab + (rm + g) * GSTRH + kk + 2 * tg);
                a[mi][1] = ld_u32h(Ab + (rm + 8 + g) * GSTRH + kk + 2 * tg);
                a[mi][2] = ld_u32h(Ab + (rm + g) * GSTRH + kk + 2 * tg + 8);
                a[mi][3] = ld_u32h(Ab + (rm + 8 + g) * GSTRH + kk + 2 * tg + 8);
            }
#pragma unroll
            for (int ni = 0; ni < 4; ni++) {
                const int nb = warp_n * 32 + ni * 8;
                uint32_t b0 = ld_u32h(Wb + (nb + g) * GSTRH + kk + 2 * tg);
                uint32_t b1 = ld_u32h(Wb + (nb + g) * GSTRH + kk + 2 * tg + 8);
#pragma unroll
                for (int mi = 0; mi < 4; mi++)
                    mma_f16(acc[mi][ni], a[mi][0], a[mi][1], a[mi][2], a[mi][3],
                            b0, b1);
            }
        }
    }

#pragma unroll
    for (int mi = 0; mi < 4; mi++) {
#pragma unroll
        for (int ni = 0; ni < 4; ni++) {
            const int r = row0 + warp_m * 64 + mi * 16 + g;
            const int c = col0 + warp_n * 32 + ni * 8 + 2 * tg;
            const float v0 = acc[mi][ni][0] * sc, v1 = acc[mi][ni][1] * sc;
            const float v2 = acc[mi][ni][2] * sc, v3 = acc[mi][ni][3] * sc;
            if (OUT_FLOAT) {
                float* Cf = (float*)C;
                *(float2*)(Cf + (size_t)r * D_MODEL + c) = make_float2(v0, v1);
                *(float2*)(Cf + (size_t)(r + 8) * D_MODEL + c) = make_float2(v2, v3);
            } else {
                __half* Ch = (__half*)C;
                *(__half2*)(Ch + (size_t)r * D_MODEL + c) =
                    __floats2half2_rn(v0, v1);
                *(__half2*)(Ch + (size_t)(r + 8) * D_MODEL + c) =
                    __floats2half2_rn(v2, v3);
            }
        }
    }
}

// ---------------------------------------------------------------------------
// Split-KV flash attention, fp16 mma (m16n8k16). Br=128, Bc=64, 128 threads
// = 4 warps, warp owns 32 q-rows (two 16-row mma tiles). Q pre-scaled by
// 1/sqrt(d) in the projection, so the common (unmasked) path has NO
// elementwise pass between mma and softmax; mask applied only on diagonal
// iterations (warp-uniform branch). PV A-frags straight from lane-local
// sacc; V B-frags via ldmatrix.x2.trans. O partials stored HALF.
// ---------------------------------------------------------------------------
#define ASTR 72
#define SMEM_ATTNH ((128 + 128 + 128) * ASTR * 2)

__global__ void __launch_bounds__(128, 2)
    attn_kernel(const __half* __restrict__ Qg, const __half* __restrict__ Kg,
                const __half* __restrict__ Vg, __half* __restrict__ Op,
                float* __restrict__ Mp, float* __restrict__ Lp, int SEQ) {
    extern __shared__ __half smb[];
    __half* Qs = smb;                       // [128][ASTR]
    __half* Ks = smb + 128 * ASTR;          // [2][64][ASTR]
    __half* Vs = Ks + 2 * 64 * ASTR;        // [2][64][ASTR]

    const int tid = threadIdx.x;
    const int lane = tid & 31, wid = tid >> 5;
    const int g = lane >> 2, tg = lane & 3;
    const int r0 = wid * 32;                 // warp's 32 q-rows
    const int bh = blockIdx.x & 15;
    const int item = blockIdx.x >> 4;
    const int qb = c_qb[item];
    const int ch = c_ch[item];
    const int b = bh >> 3, h = bh & 7;
    const size_t rowbase = (size_t)b * SEQ;
    const int colh = h * DH;
    const int kbmax = 2 * qb + 1;
    const int kb0 = ch * 8;
    const int kbe = min(kb0 + 7, kbmax);

    auto load_kv = [&](int kb, int st) {
        const __half* Kb = Kg + (rowbase + kb * 64) * D_MODEL + colh;
        const __half* Vb = Vg + (rowbase + kb * 64) * D_MODEL + colh;
        __half* Kd = Ks + st * 64 * ASTR;
        __half* Vd = Vs + st * 64 * ASTR;
#pragma unroll
        for (int i = 0; i < 4; i++) {
            const int f = tid + i * 128;      // 512 16B-chunks per matrix
            const int r = f >> 3, c8 = (f & 7) * 8;
            cp_async16(Kd + r * ASTR + c8, Kb + (size_t)r * D_MODEL + c8);
            cp_async16(Vd + r * ASTR + c8, Vb + (size_t)r * D_MODEL + c8);
        }
        CP_COMMIT();
    };

    load_kv(kb0, kb0 & 1);

    // Stage Q tile [128 x 64] halves (1024 16B-chunks).
#pragma unroll
    for (int i = 0; i < 8; i++) {
        const int f = tid + i * 128;
        const int r = f >> 3, c8 = (f & 7) * 8;
        float4 v = *(const float4*)(Qg + (rowbase + qb * 128 + r) * D_MODEL + colh + c8);
        *(float4*)(Qs + r * ASTR + c8) = v;
    }

    float m[4] = {-1e30f, -1e30f, -1e30f, -1e30f};
    float l[4] = {0.f, 0.f, 0.f, 0.f};
    float oacc[8][2][4];
#pragma unroll
    for (int ni = 0; ni < 8; ni++)
#pragma unroll
        for (int rt = 0; rt < 2; rt++)
#pragma unroll
            for (int c = 0; c < 4; c++) oacc[ni][rt][c] = 0.f;

    for (int kb = kb0; kb <= kbe; kb++) {
        CP_WAIT0();
        __syncthreads();
        if (kb + 1 <= kbe) load_kv(kb + 1, (kb + 1) & 1);

        const __half* Kb = Ks + (kb & 1) * 64 * ASTR;
        const __half* Vb = Vs + (kb & 1) * 64 * ASTR;
        const uint32_t vb_base = (uint32_t)__cvta_generic_to_shared(Vb);

        const int joff = kb * 64 - qb * 128;
        if (joff > r0 + 31) continue;           // warp fully masked
        const bool need_mask = (joff + 63 > r0);

        float sacc[8][2][4];
#pragma unroll
        for (int ni = 0; ni < 8; ni++)
#pragma unroll
            for (int rt = 0; rt < 2; rt++)
#pragma unroll
                for (int c = 0; c < 4; c++) sacc[ni][rt][c] = 0.f;

        // S = (Q/sqrt(d)) K^T : 4 k16-steps. K fragments shared across rt.
#pragma unroll
        for (int ks = 0; ks < 4; ks++) {
            const int kk = ks * 16;
            uint32_t a[2][4];
#pragma unroll
            for (int rt = 0; rt < 2; rt++) {
                const int rr = r0 + rt * 16;
                a[rt][0] = ld_u32h(Qs + (rr + g) * ASTR + kk + 2 * tg);
                a[rt][1] = ld_u32h(Qs + (rr + 8 + g) * ASTR + kk + 2 * tg);
                a[rt][2] = ld_u32h(Qs + (rr + g) * ASTR + kk + 2 * tg + 8);
                a[rt][3] = ld_u32h(Qs + (rr + 8 + g) * ASTR + kk + 2 * tg + 8);
            }
#pragma unroll
            for (int ni = 0; ni < 8; ni++) {
                uint32_t b0 = ld_u32h(Kb + (ni * 8 + g) * ASTR + kk + 2 * tg);
                uint32_t b1 = ld_u32h(Kb + (ni * 8 + g) * ASTR + kk + 2 * tg + 8);
                mma_f16(sacc[ni][0], a[0][0], a[0][1], a[0][2], a[0][3], b0, b1);
                mma_f16(sacc[ni][1], a[1][0], a[1][1], a[1][2], a[1][3], b0, b1);
            }
        }

        // causal mask only on diagonal iterations (warp-uniform branch).
        // Reference's (x-1e10)/scale underflows expf to 0 == -1e30 here.
        if (need_mask) {
#pragma unroll
            for (int ni = 0; ni < 8; ni++)
#pragma unroll
                for (int rt = 0; rt < 2; rt++)
#pragma unroll
                    for (int c = 0; c < 4; c++) {
                        const int j = joff + ni * 8 + 2 * tg + (c & 1);
                        const int r = r0 + rt * 16 + (c >> 1) * 8 + g;
                        if (j > r) sacc[ni][rt][c] = -1e30f;
                    }
        }

        // online softmax per row-group rg = rt*2 + (c>>1)
#pragma unroll
        for (int rg = 0; rg < 4; rg++) {
            const int rt = rg >> 1, ci = (rg & 1) * 2;
            float rmax = -1e30f;
#pragma unroll
            for (int ni = 0; ni < 8; ni++)
                rmax = fmaxf(rmax, fmaxf(sacc[ni][rt][ci], sacc[ni][rt][ci + 1]));
            rmax = fmaxf(rmax, __shfl_xor_sync(0xffffffffu, rmax, 1));
            rmax = fmaxf(rmax, __shfl_xor_sync(0xffffffffu, rmax, 2));
            const float mnew = fmaxf(m[rg], rmax);
            const float corr = __expf(m[rg] - mnew);
            float rsum = 0.f;
#pragma unroll
            for (int ni = 0; ni < 8; ni++) {
                float p0 = __expf(sacc[ni][rt][ci] - mnew);
                float p1 = __expf(sacc[ni][rt][ci + 1] - mnew);
                sacc[ni][rt][ci] = p0;
                sacc[ni][rt][ci + 1] = p1;
                rsum += p0 + p1;
            }
            rsum += __shfl_xor_sync(0xffffffffu, rsum, 1);
            rsum += __shfl_xor_sync(0xffffffffu, rsum, 2);
            l[rg] = l[rg] * corr + rsum;
            m[rg] = mnew;
#pragma unroll
            for (int ni = 0; ni < 8; ni++) {
                oacc[ni][rt][ci] *= corr;
                oacc[ni][rt][ci + 1] *= corr;
            }
        }

        // O += P V : A-frags from lane-local sacc (k16 alignment);
        // V B-frags via ldmatrix.x2.trans.
#pragma unroll
        for (int ks = 0; ks < 4; ks++) {
            const int j0 = ks * 16;
            uint32_t aA[2][4];
#pragma unroll
            for (int rt = 0; rt < 2; rt++) {
                aA[rt][0] = pk2h(sacc[2 * ks][rt][0], sacc[2 * ks][rt][1]);
                aA[rt][1] = pk2h(sacc[2 * ks][rt][2], sacc[2 * ks][rt][3]);
                aA[rt][2] = pk2h(sacc[2 * ks + 1][rt][0], sacc[2 * ks + 1][rt][1]);
                aA[rt][3] = pk2h(sacc[2 * ks + 1][rt][2], sacc[2 * ks + 1][rt][3]);
            }
            const uint32_t row_addr =
                vb_base + ((j0 + (lane & 15)) * ASTR) * 2;
#pragma unroll
            for (int ni = 0; ni < 8; ni++) {
                uint32_t b0, b1;
                asm volatile(
                    "ldmatrix.sync.aligned.m8n8.x2.trans.shared.b16 {%0,%1}, [%2];"
                    : "=r"(b0), "=r"(b1)
                    : "r"(row_addr + ni * 16));
                mma_f16(oacc[ni][0], aA[0][0], aA[0][1], aA[0][2], aA[0][3], b0, b1);
                mma_f16(oacc[ni][1], aA[1][0], aA[1][1], aA[1][2], aA[1][3], b0, b1);
            }
        }
    }

    // Write UNNORMALIZED partials (half) + (m, l) fp32
    __half* op = Op + (size_t)ch * 4096 * 512;
#pragma unroll
    for (int rt = 0; rt < 2; rt++) {
        const size_t rA = rowbase + qb * 128 + r0 + rt * 16 + g;
#pragma unroll
        for (int ni = 0; ni < 8; ni++) {
            const int c = colh + ni * 8 + 2 * tg;
            *(__half2*)(op + rA * D_MODEL + c) =
                __floats2half2_rn(oacc[ni][rt][0], oacc[ni][rt][1]);
            *(__half2*)(op + (rA + 8) * D_MODEL + c) =
                __floats2half2_rn(oacc[ni][rt][2], oacc[ni][rt][3]);
        }
        if (tg == 0) {
            const size_t mlb = (size_t)(ch * 8 + h) * 4096;
            Mp[mlb + rA] = m[rt * 2];
            Lp[mlb + rA] = l[rt * 2];
            Mp[mlb + rA + 8] = m[rt * 2 + 1];
            Lp[mlb + rA + 8] = l[rt * 2 + 1];
        }
    }
}

// ---------------------------------------------------------------------------
// Combine split-KV partials (half O, fp32 m/l): exact softmax merge in fp32,
// normalize, store half.
// ---------------------------------------------------------------------------
__global__ void __launch_bounds__(256) combine_kernel(
    const __half* __restrict__ Op, const float* __restrict__ Mp,
    const float* __restrict__ Lp, __half* __restrict__ Og) {
    const int tid = threadIdx.x;
    const int u = blockIdx.x * 8 + (tid >> 5);  // (row, head) unit
    const int row = u >> 3, h = u & 7;
    const int j = (tid & 31) * 2;
    const int qb = (row >> 7) & 15;
    const int nch = (qb >> 2) + 1;

    float mv[4], lv[4];
    float mg = -1e30f;
#pragma unroll
    for (int c = 0; c < 4; c++)
        if (c < nch) {
            mv[c] = Mp[(size_t)(c * 8 + h) * 4096 + row];
            lv[c] = Lp[(size_t)(c * 8 + h) * 4096 + row];
            mg = fmaxf(mg, mv[c]);
        }
    float lg = 0.f;
    float2 o = make_float2(0.f, 0.f);
#pragma unroll
    for (int c = 0; c < 4; c++)
        if (c < nch) {
            const float sc = __expf(mv[c] - mg);
            lg += sc * lv[c];
            float2 p = __half22float2(*(const __half2*)(
                Op + (size_t)c * 4096 * 512 + (size_t)row * 512 + h * 64 + j));
            o.x += sc * p.x;
            o.y += sc * p.y;
        }
    const float inv = 1.f / lg;
    *(__half2*)(Og + (size_t)row * 512 + h * 64 + j) =
        __floats2half2_rn(o.x * inv, o.y * inv);
}

// ---------------------------------------------------------------------------
extern "C" void kernel_launch(void* const* d_in, const int* in_sizes, int n_in,
                              void* d_out, int out_size) {
    const float* q  = (const float*)d_in[0];
    const float* k  = (const float*)d_in[1];
    const float* v  = (const float*)d_in[2];
    const float* wq = (const float*)d_in[3];
    const float* wk = (const float*)d_in[4];
    const float* wv = (const float*)d_in[5];
    const float* wo = (const float*)d_in[6];
    float* out = (float*)d_out;

    const int M = in_sizes[0] / D_MODEL;  // B*S = 4096
    const int B = 2;
    const int SEQ = M / B;                // 2048

    __half *gqh, *gkh, *gvh, *gah, *gxh, *gwh, *goph;
    float *gm, *gl;
    cudaGetSymbolAddress((void**)&gqh, g_qh);
    cudaGetSymbolAddress((void**)&gkh, g_kh);
    cudaGetSymbolAddress((void**)&gvh, g_vh);
    cudaGetSymbolAddress((void**)&gah, g_ah);
    cudaGetSymbolAddress((void**)&gxh, g_xh);
    cudaGetSymbolAddress((void**)&gwh, g_wh);
    cudaGetSymbolAddress((void**)&goph, g_oph);
    cudaGetSymbolAddress((void**)&gm, g_m);
    cudaGetSymbolAddress((void**)&gl, g_l);

    cudaFuncSetAttribute(gemm_h<0>, cudaFuncAttributeMaxDynamicSharedMemorySize,
                         SMEM_GEMMH);
    cudaFuncSetAttribute(gemm_h<1>, cudaFuncAttributeMaxDynamicSharedMemorySize,
                         SMEM_GEMMH);
    cudaFuncSetAttribute(attn_kernel, cudaFuncAttributeMaxDynamicSharedMemorySize,
                         SMEM_ATTNH);

    // Convert weights + inputs fp32 -> half (RN).
    conv_w<<<1024, 256>>>((const float4*)wq, (const float4*)wk,
                          (const float4*)wv, (const float4*)wo, gwh);
    conv_in<<<6144, 256>>>((const float4*)q, (const float4*)k, (const float4*)v,
                           gxh);
    const __half* xq = gxh;
    const __half* xk = gxh + 2097152;
    const __half* xv = gxh + 4194304;
    const __half* hwq = gwh;
    const __half* hwk = gwh + 512 * 512;
    const __half* hwv = gwh + 2 * 512 * 512;
    const __half* hwo = gwh + 3 * 512 * 512;

    // Fused projections (fp16 mma), half outputs; Q scaled by 1/sqrt(512).
    dim3 gg3(M / 128, D_MODEL / 128, 3);
    gemm_h<0><<<gg3, 256, SMEM_GEMMH>>>(xq, hwq, gqh, xk, hwk, gkh, xv, hwv,
                                        gvh, 0.044194173824159216f);

    // Split-KV attention: 40 heavy-first items x 16 bh (item-major), 128 thr.
    attn_kernel<<<16 * 40, 128, SMEM_ATTNH>>>(gqh, gkh, gvh, goph, gm, gl, SEQ);

    // Combine partials -> half attn output.
    combine_kernel<<<4096 * 8 / 8, 256>>>(goph, gm, gl, gah);

    // Output projection (fp16 mma), fp32 output.
    dim3 gg1(M / 128, D_MODEL / 128, 1);
    gemm_h<1><<<gg1, 256, SMEM_GEMMH>>>(gah, hwo, out, gah, hwo, out, gah, hwo,
                                        out, 1.f);
}